// round 2
// baseline (speedup 1.0000x reference)
#include <cuda_runtime.h>

// ---------------------------------------------------------------------------
// SparseConvNet on GB300 — round 0: list-compacted fp32 conv with f32x2 FFMA2
// Layouts: all intermediate feature volumes are channels-last [z][y][x][c].
// Masked-out voxels are never written; __device__ globals are zero-initialized
// at module load, so they stay exactly 0.0f forever (deterministic replays).
// ---------------------------------------------------------------------------

#define N0 (128*128*128)
#define N1 (64*64*64)

typedef unsigned long long u64;

__device__ float g_h0a[16u * N0];   // stage1 out (128^3 x 16)
__device__ float g_h0b[16u * N0];   // stage2 out
__device__ float g_h1a[32u * N1];   // stage3 out (64^3 x 32)
__device__ float g_h1b[32u * N1];   // stage4 out
__device__ float g_h1c[32u * N1];   // stage5 out
__device__ int   g_list0[N0];
__device__ int   g_list1[N1];
__device__ int   g_cnt[2];

// ---- packed f32x2 helpers (sm_100+): 2 fp32 FMAs per issue slot -----------
__device__ __forceinline__ u64 pack2(float lo, float hi) {
    u64 d; asm("mov.b64 %0, {%1, %2};" : "=l"(d) : "f"(lo), "f"(hi)); return d;
}
__device__ __forceinline__ void unpack2(u64 v, float& lo, float& hi) {
    asm("mov.b64 {%0, %1}, %2;" : "=f"(lo), "=f"(hi) : "l"(v));
}
__device__ __forceinline__ u64 ffma2(u64 a, u64 b, u64 c) {
    u64 r; asm("fma.rn.f32x2 %0, %1, %2, %3;" : "=l"(r) : "l"(a), "l"(b), "l"(c));
    return r;
}

// ---------------------------------------------------------------------------
__global__ void zero_cnt_k() { g_cnt[0] = 0; g_cnt[1] = 0; }

// Build level-0 active-voxel list (warp-aggregated atomics).
__global__ void build_list0_k(const int* __restrict__ mask) {
    int i = blockIdx.x * blockDim.x + threadIdx.x;   // grid exactly covers N0
    bool act = mask[i] != 0;
    unsigned b = __ballot_sync(0xffffffffu, act);
    if (!b) return;
    int lane = threadIdx.x & 31;
    int leader = __ffs(b) - 1;
    int pos = 0;
    if (lane == leader) pos = atomicAdd(&g_cnt[0], __popc(b));
    pos = __shfl_sync(0xffffffffu, pos, leader);
    if (act) g_list0[pos + __popc(b & ((1u << lane) - 1u))] = i;
}

// Build level-1 list: m1 = maxpool3x3x3 stride2 pad1 of m0.
__global__ void build_list1_k(const int* __restrict__ mask) {
    int i = blockIdx.x * blockDim.x + threadIdx.x;   // grid exactly covers N1
    int z = i >> 12, y = (i >> 6) & 63, x = i & 63;
    int act = 0;
    #pragma unroll
    for (int t = 0; t < 27; t++) {
        int zz = 2 * z + t / 9 - 1;
        int yy = 2 * y + (t / 3) % 3 - 1;
        int xx = 2 * x + t % 3 - 1;
        if ((unsigned)zz < 128u && (unsigned)yy < 128u && (unsigned)xx < 128u)
            act |= mask[(zz << 14) | (yy << 7) | xx];
    }
    unsigned b = __ballot_sync(0xffffffffu, act != 0);
    if (!b) return;
    int lane = threadIdx.x & 31;
    int leader = __ffs(b) - 1;
    int pos = 0;
    if (lane == leader) pos = atomicAdd(&g_cnt[1], __popc(b));
    pos = __shfl_sync(0xffffffffu, pos, leader);
    if (act) g_list1[pos + __popc(b & ((1u << lane) - 1u))] = i;
}

// ---------------------------------------------------------------------------
// Stage 1: conv 3 -> 16 over masked x_feat (channel-first input), 128^3.
__global__ void __launch_bounds__(256) stage1_k(
    const float* __restrict__ xf, const int* __restrict__ mask,
    const float* __restrict__ w, const float* __restrict__ sc,
    const float* __restrict__ sh)
{
    __shared__ u64 sw[27 * 3 * 8];            // [t][ci][co_pair]
    int n = g_cnt[0];
    if ((int)(blockIdx.x * 256) >= n) return;
    float* swf = (float*)sw;
    for (int idx = threadIdx.x; idx < 16 * 3 * 27; idx += 256) {
        int co = idx / 81, r = idx % 81, ci = r / 27, t = r % 27;
        swf[((t * 3 + ci) * 8 + (co >> 1)) * 2 + (co & 1)] = w[idx];
    }
    __syncthreads();
    int gid = blockIdx.x * 256 + threadIdx.x;
    if (gid >= n) return;
    int vox = g_list0[gid];
    int z = vox >> 14, y = (vox >> 7) & 127, x = vox & 127;
    u64 acc[8];
    #pragma unroll
    for (int p = 0; p < 8; p++) acc[p] = 0ull;
    for (int t = 0; t < 27; t++) {
        int zz = z + t / 9 - 1, yy = y + (t / 3) % 3 - 1, xx = x + t % 3 - 1;
        if ((unsigned)zz >= 128u || (unsigned)yy >= 128u || (unsigned)xx >= 128u) continue;
        int nb = (zz << 14) | (yy << 7) | xx;
        if (!mask[nb]) continue;                       // x_feat * m0
        const u64* wp = &sw[t * 24];
        #pragma unroll
        for (int ci = 0; ci < 3; ci++) {
            float xv = xf[(size_t)ci * N0 + nb];
            u64 xv2 = pack2(xv, xv);
            #pragma unroll
            for (int p = 0; p < 8; p++) acc[p] = ffma2(wp[ci * 8 + p], xv2, acc[p]);
        }
    }
    float* op = &g_h0a[(size_t)vox * 16];
    #pragma unroll
    for (int p = 0; p < 8; p++) {
        float a0, a1; unpack2(acc[p], a0, a1);
        op[2 * p]     = fmaxf(fmaf(a0, sc[2 * p],     sh[2 * p]),     0.f);
        op[2 * p + 1] = fmaxf(fmaf(a1, sc[2 * p + 1], sh[2 * p + 1]), 0.f);
    }
}

// ---------------------------------------------------------------------------
// Same-resolution conv, CIN -> 2*COP channels, channels-last in/out.
// LEVEL selects list0/list1; CHECK skips zero neighbors via the level-0 mask.
template <int CIN, int COP, int DIM, int LEVEL, bool CHECK>
__global__ void __launch_bounds__(256) conv_same_k(
    const float* __restrict__ in, const int* __restrict__ mask,
    const float* __restrict__ w, const float* __restrict__ sc,
    const float* __restrict__ sh, float* __restrict__ out)
{
    extern __shared__ u64 sw[];               // [t][ci][co_pair]
    constexpr int SB = (DIM == 128) ? 7 : 6;
    constexpr int CO = COP * 2;
    int n = g_cnt[LEVEL];
    if ((int)(blockIdx.x * 256) >= n) return;
    float* swf = (float*)sw;
    for (int idx = threadIdx.x; idx < CO * CIN * 27; idx += 256) {
        int co = idx / (CIN * 27), ci = (idx / 27) % CIN, t = idx % 27;
        swf[((t * CIN + ci) * COP + (co >> 1)) * 2 + (co & 1)] = w[idx];
    }
    __syncthreads();
    int gid = blockIdx.x * 256 + threadIdx.x;
    if (gid >= n) return;
    const int* lst = LEVEL ? g_list1 : g_list0;
    int vox = lst[gid];
    int z = vox >> (2 * SB), y = (vox >> SB) & (DIM - 1), x = vox & (DIM - 1);
    u64 acc[COP];
    #pragma unroll
    for (int p = 0; p < COP; p++) acc[p] = 0ull;
    for (int t = 0; t < 27; t++) {
        int zz = z + t / 9 - 1, yy = y + (t / 3) % 3 - 1, xx = x + t % 3 - 1;
        if ((unsigned)zz >= (unsigned)DIM || (unsigned)yy >= (unsigned)DIM ||
            (unsigned)xx >= (unsigned)DIM) continue;
        int nb = (zz << (2 * SB)) | (yy << SB) | xx;
        if (CHECK) { if (!mask[nb]) continue; }
        float xin[CIN];
        const float4* ip = (const float4*)(in + (size_t)nb * CIN);
        #pragma unroll
        for (int q = 0; q < CIN / 4; q++) ((float4*)xin)[q] = ip[q];
        const u64* wp = &sw[t * CIN * COP];
        #pragma unroll
        for (int ci = 0; ci < CIN; ci++) {
            u64 xv2 = pack2(xin[ci], xin[ci]);
            #pragma unroll
            for (int p = 0; p < COP; p++) acc[p] = ffma2(wp[ci * COP + p], xv2, acc[p]);
        }
    }
    float* op = out + (size_t)vox * CO;
    #pragma unroll
    for (int p = 0; p < COP; p++) {
        float a0, a1; unpack2(acc[p], a0, a1);
        op[2 * p]     = fmaxf(fmaf(a0, sc[2 * p],     sh[2 * p]),     0.f);
        op[2 * p + 1] = fmaxf(fmaf(a1, sc[2 * p + 1], sh[2 * p + 1]), 0.f);
    }
}

// ---------------------------------------------------------------------------
// Strided (stride-2) conv: 16 (128^3) -> 32 (64^3), level-1 output list.
template <int CIN, int COP>
__global__ void __launch_bounds__(256) conv_down_k(
    const float* __restrict__ in, const int* __restrict__ mask,
    const float* __restrict__ w, const float* __restrict__ sc,
    const float* __restrict__ sh, float* __restrict__ out)
{
    extern __shared__ u64 sw[];
    constexpr int CO = COP * 2;
    int n = g_cnt[1];
    if ((int)(blockIdx.x * 256) >= n) return;
    float* swf = (float*)sw;
    for (int idx = threadIdx.x; idx < CO * CIN * 27; idx += 256) {
        int co = idx / (CIN * 27), ci = (idx / 27) % CIN, t = idx % 27;
        swf[((t * CIN + ci) * COP + (co >> 1)) * 2 + (co & 1)] = w[idx];
    }
    __syncthreads();
    int gid = blockIdx.x * 256 + threadIdx.x;
    if (gid >= n) return;
    int vox = g_list1[gid];
    int z = vox >> 12, y = (vox >> 6) & 63, x = vox & 63;
    u64 acc[COP];
    #pragma unroll
    for (int p = 0; p < COP; p++) acc[p] = 0ull;
    for (int t = 0; t < 27; t++) {
        int zz = 2 * z + t / 9 - 1;
        int yy = 2 * y + (t / 3) % 3 - 1;
        int xx = 2 * x + t % 3 - 1;
        if ((unsigned)zz >= 128u || (unsigned)yy >= 128u || (unsigned)xx >= 128u) continue;
        int nb = (zz << 14) | (yy << 7) | xx;
        if (!mask[nb]) continue;                        // input is level-0 sparse
        float xin[CIN];
        const float4* ip = (const float4*)(in + (size_t)nb * CIN);
        #pragma unroll
        for (int q = 0; q < CIN / 4; q++) ((float4*)xin)[q] = ip[q];
        const u64* wp = &sw[t * CIN * COP];
        #pragma unroll
        for (int ci = 0; ci < CIN; ci++) {
            u64 xv2 = pack2(xin[ci], xin[ci]);
            #pragma unroll
            for (int p = 0; p < COP; p++) acc[p] = ffma2(wp[ci * COP + p], xv2, acc[p]);
        }
    }
    float* op = out + (size_t)vox * CO;
    #pragma unroll
    for (int p = 0; p < COP; p++) {
        float a0, a1; unpack2(acc[p], a0, a1);
        op[2 * p]     = fmaxf(fmaf(a0, sc[2 * p],     sh[2 * p]),     0.f);
        op[2 * p + 1] = fmaxf(fmaf(a1, sc[2 * p + 1], sh[2 * p + 1]), 0.f);
    }
}

// ---------------------------------------------------------------------------
// Trilinear sampling of the final 64^3 x 32 volume at 65536 coords.
__global__ void __launch_bounds__(256) sample_k(
    const float* __restrict__ coords, const float* __restrict__ vol,
    float* __restrict__ out)
{
    int p = blockIdx.x * 256 + threadIdx.x;
    if (p >= 65536) return;
    float fx = (coords[3 * p + 0] + 1.f) * 0.5f * 63.f;
    float fy = (coords[3 * p + 1] + 1.f) * 0.5f * 63.f;
    float fz = (coords[3 * p + 2] + 1.f) * 0.5f * 63.f;
    float x0f = floorf(fx), y0f = floorf(fy), z0f = floorf(fz);
    float tx = fx - x0f, ty = fy - y0f, tz = fz - z0f;
    int x0 = (int)x0f, y0 = (int)y0f, z0 = (int)z0f;
    float acc[32];
    #pragma unroll
    for (int c = 0; c < 32; c++) acc[c] = 0.f;
    #pragma unroll
    for (int dz = 0; dz < 2; dz++)
    #pragma unroll
    for (int dy = 0; dy < 2; dy++)
    #pragma unroll
    for (int dx = 0; dx < 2; dx++) {
        int xi = x0 + dx, yi = y0 + dy, zi = z0 + dz;
        if (xi < 0 || xi >= 64 || yi < 0 || yi >= 64 || zi < 0 || zi >= 64) continue;
        float wgt = (dx ? tx : 1.f - tx) * (dy ? ty : 1.f - ty) * (dz ? tz : 1.f - tz);
        const float4* vp = (const float4*)(vol + (size_t)((zi * 64 + yi) * 64 + xi) * 32);
        #pragma unroll
        for (int q = 0; q < 8; q++) {
            float4 v = vp[q];
            acc[4 * q + 0] += v.x * wgt;
            acc[4 * q + 1] += v.y * wgt;
            acc[4 * q + 2] += v.z * wgt;
            acc[4 * q + 3] += v.w * wgt;
        }
    }
    float4* op = (float4*)(out + (size_t)p * 32);
    #pragma unroll
    for (int q = 0; q < 8; q++)
        op[q] = make_float4(acc[4 * q], acc[4 * q + 1], acc[4 * q + 2], acc[4 * q + 3]);
}

// ---------------------------------------------------------------------------
extern "C" void kernel_launch(void* const* d_in, const int* in_sizes, int n_in,
                              void* d_out, int out_size)
{
    const float* x_feat = (const float*)d_in[0];
    const int*   mask   = (const int*)d_in[1];
    const float* coords = (const float*)d_in[2];
    const float* w0a = (const float*)d_in[3];
    const float* s0a = (const float*)d_in[4];
    const float* b0a = (const float*)d_in[5];
    const float* w0b = (const float*)d_in[6];
    const float* s0b = (const float*)d_in[7];
    const float* b0b = (const float*)d_in[8];
    const float* wd0 = (const float*)d_in[9];
    const float* sd0 = (const float*)d_in[10];
    const float* bd0 = (const float*)d_in[11];
    const float* w1a = (const float*)d_in[12];
    const float* s1a = (const float*)d_in[13];
    const float* b1a = (const float*)d_in[14];
    const float* w1b = (const float*)d_in[15];
    const float* s1b = (const float*)d_in[16];
    const float* b1b = (const float*)d_in[17];
    float* out = (float*)d_out;

    float *h0a, *h0b, *h1a, *h1b, *h1c;
    cudaGetSymbolAddress((void**)&h0a, g_h0a);
    cudaGetSymbolAddress((void**)&h0b, g_h0b);
    cudaGetSymbolAddress((void**)&h1a, g_h1a);
    cudaGetSymbolAddress((void**)&h1b, g_h1b);
    cudaGetSymbolAddress((void**)&h1c, g_h1c);

    cudaFuncSetAttribute(conv_down_k<16, 16>,
                         cudaFuncAttributeMaxDynamicSharedMemorySize, 27 * 16 * 16 * 8);
    cudaFuncSetAttribute(conv_same_k<32, 16, 64, 1, false>,
                         cudaFuncAttributeMaxDynamicSharedMemorySize, 27 * 32 * 16 * 8);

    zero_cnt_k<<<1, 1>>>();
    build_list0_k<<<N0 / 256, 256>>>(mask);
    build_list1_k<<<N1 / 256, 256>>>(mask);
    stage1_k<<<N0 / 256, 256>>>(x_feat, mask, w0a, s0a, b0a);
    conv_same_k<16, 8, 128, 0, true>
        <<<N0 / 256, 256, 27 * 16 * 8 * 8>>>(h0a, mask, w0b, s0b, b0b, h0b);
    conv_down_k<16, 16>
        <<<N1 / 256, 256, 27 * 16 * 16 * 8>>>(h0b, mask, wd0, sd0, bd0, h1a);
    conv_same_k<32, 16, 64, 1, false>
        <<<N1 / 256, 256, 27 * 32 * 16 * 8>>>(h1a, nullptr, w1a, s1a, b1a, h1b);
    conv_same_k<32, 16, 64, 1, false>
        <<<N1 / 256, 256, 27 * 32 * 16 * 8>>>(h1b, nullptr, w1b, s1b, b1b, h1c);
    sample_k<<<65536 / 256, 256>>>(coords, h1c, out);
}

// round 3
// speedup vs baseline: 1.3194x; 1.3194x over previous
#include <cuda_runtime.h>

// ---------------------------------------------------------------------------
// SparseConvNet on GB300 — round 2: channel-PLANE layout [C/4][vox][4]
// so warp loads of one plane at consecutive voxels are fully coalesced.
// Masked-out voxels are never written; __device__ globals are zero-initialized
// at module load, so they stay exactly 0.0f forever (deterministic replays).
// ---------------------------------------------------------------------------

#define N0 (128*128*128)
#define N1 (64*64*64)

typedef unsigned long long u64;

__device__ float4 g_h0a[4u * N0];   // stage1 out (128^3 x 16) as 4 planes
__device__ float4 g_h0b[4u * N0];   // stage2 out
__device__ float4 g_h1a[8u * N1];   // stage3 out (64^3 x 32) as 8 planes
__device__ float4 g_h1b[8u * N1];   // stage4 out
__device__ float4 g_h1c[8u * N1];   // stage5 out
__device__ int   g_list0[N0];
__device__ int   g_list1[N1];
__device__ int   g_cnt[2];

// ---- packed f32x2 helpers (sm_100+): 2 fp32 FMAs per issue slot -----------
__device__ __forceinline__ u64 pack2(float lo, float hi) {
    u64 d; asm("mov.b64 %0, {%1, %2};" : "=l"(d) : "f"(lo), "f"(hi)); return d;
}
__device__ __forceinline__ void unpack2(u64 v, float& lo, float& hi) {
    asm("mov.b64 {%0, %1}, %2;" : "=f"(lo), "=f"(hi) : "l"(v));
}
__device__ __forceinline__ u64 ffma2(u64 a, u64 b, u64 c) {
    u64 r; asm("fma.rn.f32x2 %0, %1, %2, %3;" : "=l"(r) : "l"(a), "l"(b), "l"(c));
    return r;
}

// ---------------------------------------------------------------------------
__global__ void zero_cnt_k() { g_cnt[0] = 0; g_cnt[1] = 0; }

// Build level-0 active-voxel list (warp-aggregated atomics).
__global__ void build_list0_k(const int* __restrict__ mask) {
    int i = blockIdx.x * blockDim.x + threadIdx.x;   // grid exactly covers N0
    bool act = mask[i] != 0;
    unsigned b = __ballot_sync(0xffffffffu, act);
    if (!b) return;
    int lane = threadIdx.x & 31;
    int leader = __ffs(b) - 1;
    int pos = 0;
    if (lane == leader) pos = atomicAdd(&g_cnt[0], __popc(b));
    pos = __shfl_sync(0xffffffffu, pos, leader);
    if (act) g_list0[pos + __popc(b & ((1u << lane) - 1u))] = i;
}

// Build level-1 list: m1 = maxpool3x3x3 stride2 pad1 of m0.
__global__ void build_list1_k(const int* __restrict__ mask) {
    int i = blockIdx.x * blockDim.x + threadIdx.x;   // grid exactly covers N1
    int z = i >> 12, y = (i >> 6) & 63, x = i & 63;
    int act = 0;
    #pragma unroll
    for (int t = 0; t < 27; t++) {
        int zz = 2 * z + t / 9 - 1;
        int yy = 2 * y + (t / 3) % 3 - 1;
        int xx = 2 * x + t % 3 - 1;
        if ((unsigned)zz < 128u && (unsigned)yy < 128u && (unsigned)xx < 128u)
            act |= mask[(zz << 14) | (yy << 7) | xx];
    }
    unsigned b = __ballot_sync(0xffffffffu, act != 0);
    if (!b) return;
    int lane = threadIdx.x & 31;
    int leader = __ffs(b) - 1;
    int pos = 0;
    if (lane == leader) pos = atomicAdd(&g_cnt[1], __popc(b));
    pos = __shfl_sync(0xffffffffu, pos, leader);
    if (act) g_list1[pos + __popc(b & ((1u << lane) - 1u))] = i;
}

// ---------------------------------------------------------------------------
// Stage 1: conv 3 -> 16 over masked x_feat (channel-first input), 128^3.
// Output: 4 float4 planes.
__global__ void __launch_bounds__(256) stage1_k(
    const float* __restrict__ xf, const int* __restrict__ mask,
    const float* __restrict__ w, const float* __restrict__ sc,
    const float* __restrict__ sh)
{
    __shared__ u64 sw[27 * 3 * 8];            // [t][ci][co_pair]
    int n = g_cnt[0];
    if ((int)(blockIdx.x * 256) >= n) return;
    float* swf = (float*)sw;
    for (int idx = threadIdx.x; idx < 16 * 3 * 27; idx += 256) {
        int co = idx / 81, r = idx % 81, ci = r / 27, t = r % 27;
        swf[((t * 3 + ci) * 8 + (co >> 1)) * 2 + (co & 1)] = w[idx];
    }
    __syncthreads();
    int gid = blockIdx.x * 256 + threadIdx.x;
    if (gid >= n) return;
    int vox = g_list0[gid];
    int z = vox >> 14, y = (vox >> 7) & 127, x = vox & 127;
    u64 acc[8];
    #pragma unroll
    for (int p = 0; p < 8; p++) acc[p] = 0ull;
    for (int t = 0; t < 27; t++) {
        int zz = z + t / 9 - 1, yy = y + (t / 3) % 3 - 1, xx = x + t % 3 - 1;
        if ((unsigned)zz >= 128u || (unsigned)yy >= 128u || (unsigned)xx >= 128u) continue;
        int nb = (zz << 14) | (yy << 7) | xx;
        if (!mask[nb]) continue;                       // x_feat * m0
        const u64* wp = &sw[t * 24];
        #pragma unroll
        for (int ci = 0; ci < 3; ci++) {
            float xv = xf[(size_t)ci * N0 + nb];
            u64 xv2 = pack2(xv, xv);
            #pragma unroll
            for (int p = 0; p < 8; p++) acc[p] = ffma2(wp[ci * 8 + p], xv2, acc[p]);
        }
    }
    #pragma unroll
    for (int q = 0; q < 4; q++) {
        float a0, a1, a2, a3;
        unpack2(acc[2 * q],     a0, a1);
        unpack2(acc[2 * q + 1], a2, a3);
        float4 o;
        o.x = fmaxf(fmaf(a0, sc[4 * q + 0], sh[4 * q + 0]), 0.f);
        o.y = fmaxf(fmaf(a1, sc[4 * q + 1], sh[4 * q + 1]), 0.f);
        o.z = fmaxf(fmaf(a2, sc[4 * q + 2], sh[4 * q + 2]), 0.f);
        o.w = fmaxf(fmaf(a3, sc[4 * q + 3], sh[4 * q + 3]), 0.f);
        g_h0a[(size_t)q * N0 + vox] = o;
    }
}

// ---------------------------------------------------------------------------
// Same-resolution conv, CIN -> 2*COP channels, channel-plane in/out.
// LEVEL selects list0/list1; CHECK skips zero neighbors via the level-0 mask.
template <int CIN, int COP, int DIM, int LEVEL, bool CHECK>
__global__ void __launch_bounds__(256) conv_same_k(
    const float4* __restrict__ in4, const int* __restrict__ mask,
    const float* __restrict__ w, const float* __restrict__ sc,
    const float* __restrict__ sh, float4* __restrict__ out4)
{
    extern __shared__ u64 sw[];               // [t][ci][co_pair]
    constexpr int SB = (DIM == 128) ? 7 : 6;
    constexpr int NV = DIM * DIM * DIM;
    int n = g_cnt[LEVEL];
    if ((int)(blockIdx.x * 256) >= n) return;
    float* swf = (float*)sw;
    for (int idx = threadIdx.x; idx < 2 * COP * CIN * 27; idx += 256) {
        int co = idx / (CIN * 27), ci = (idx / 27) % CIN, t = idx % 27;
        swf[((t * CIN + ci) * COP + (co >> 1)) * 2 + (co & 1)] = w[idx];
    }
    __syncthreads();
    int gid = blockIdx.x * 256 + threadIdx.x;
    if (gid >= n) return;
    const int* lst = LEVEL ? g_list1 : g_list0;
    int vox = lst[gid];
    int z = vox >> (2 * SB), y = (vox >> SB) & (DIM - 1), x = vox & (DIM - 1);
    u64 acc[COP];
    #pragma unroll
    for (int p = 0; p < COP; p++) acc[p] = 0ull;
    for (int t = 0; t < 27; t++) {
        int zz = z + t / 9 - 1, yy = y + (t / 3) % 3 - 1, xx = x + t % 3 - 1;
        if ((unsigned)zz >= (unsigned)DIM || (unsigned)yy >= (unsigned)DIM ||
            (unsigned)xx >= (unsigned)DIM) continue;
        int nb = (zz << (2 * SB)) | (yy << SB) | xx;
        if (CHECK) { if (!mask[nb]) continue; }
        float xin[CIN];
        #pragma unroll
        for (int q = 0; q < CIN / 4; q++)
            ((float4*)xin)[q] = in4[(size_t)q * NV + nb];   // coalesced plane load
        const u64* wp = &sw[t * CIN * COP];
        #pragma unroll
        for (int ci = 0; ci < CIN; ci++) {
            u64 xv2 = pack2(xin[ci], xin[ci]);
            #pragma unroll
            for (int p = 0; p < COP; p++) acc[p] = ffma2(wp[ci * COP + p], xv2, acc[p]);
        }
    }
    #pragma unroll
    for (int q = 0; q < COP / 2; q++) {
        float a0, a1, a2, a3;
        unpack2(acc[2 * q],     a0, a1);
        unpack2(acc[2 * q + 1], a2, a3);
        float4 o;
        o.x = fmaxf(fmaf(a0, sc[4 * q + 0], sh[4 * q + 0]), 0.f);
        o.y = fmaxf(fmaf(a1, sc[4 * q + 1], sh[4 * q + 1]), 0.f);
        o.z = fmaxf(fmaf(a2, sc[4 * q + 2], sh[4 * q + 2]), 0.f);
        o.w = fmaxf(fmaf(a3, sc[4 * q + 3], sh[4 * q + 3]), 0.f);
        out4[(size_t)q * NV + vox] = o;
    }
}

// ---------------------------------------------------------------------------
// Strided (stride-2) conv: 16 (128^3) -> 32 (64^3), level-1 output list.
template <int CIN, int COP>
__global__ void __launch_bounds__(256) conv_down_k(
    const float4* __restrict__ in4, const int* __restrict__ mask,
    const float* __restrict__ w, const float* __restrict__ sc,
    const float* __restrict__ sh, float4* __restrict__ out4)
{
    extern __shared__ u64 sw[];
    int n = g_cnt[1];
    if ((int)(blockIdx.x * 256) >= n) return;
    float* swf = (float*)sw;
    for (int idx = threadIdx.x; idx < 2 * COP * CIN * 27; idx += 256) {
        int co = idx / (CIN * 27), ci = (idx / 27) % CIN, t = idx % 27;
        swf[((t * CIN + ci) * COP + (co >> 1)) * 2 + (co & 1)] = w[idx];
    }
    __syncthreads();
    int gid = blockIdx.x * 256 + threadIdx.x;
    if (gid >= n) return;
    int vox = g_list1[gid];
    int z = vox >> 12, y = (vox >> 6) & 63, x = vox & 63;
    u64 acc[COP];
    #pragma unroll
    for (int p = 0; p < COP; p++) acc[p] = 0ull;
    for (int t = 0; t < 27; t++) {
        int zz = 2 * z + t / 9 - 1;
        int yy = 2 * y + (t / 3) % 3 - 1;
        int xx = 2 * x + t % 3 - 1;
        if ((unsigned)zz >= 128u || (unsigned)yy >= 128u || (unsigned)xx >= 128u) continue;
        int nb = (zz << 14) | (yy << 7) | xx;
        if (!mask[nb]) continue;                        // input is level-0 sparse
        float xin[CIN];
        #pragma unroll
        for (int q = 0; q < CIN / 4; q++)
            ((float4*)xin)[q] = in4[(size_t)q * N0 + nb];
        const u64* wp = &sw[t * CIN * COP];
        #pragma unroll
        for (int ci = 0; ci < CIN; ci++) {
            u64 xv2 = pack2(xin[ci], xin[ci]);
            #pragma unroll
            for (int p = 0; p < COP; p++) acc[p] = ffma2(wp[ci * COP + p], xv2, acc[p]);
        }
    }
    #pragma unroll
    for (int q = 0; q < COP / 2; q++) {
        float a0, a1, a2, a3;
        unpack2(acc[2 * q],     a0, a1);
        unpack2(acc[2 * q + 1], a2, a3);
        float4 o;
        o.x = fmaxf(fmaf(a0, sc[4 * q + 0], sh[4 * q + 0]), 0.f);
        o.y = fmaxf(fmaf(a1, sc[4 * q + 1], sh[4 * q + 1]), 0.f);
        o.z = fmaxf(fmaf(a2, sc[4 * q + 2], sh[4 * q + 2]), 0.f);
        o.w = fmaxf(fmaf(a3, sc[4 * q + 3], sh[4 * q + 3]), 0.f);
        out4[(size_t)q * N1 + vox] = o;
    }
}

// ---------------------------------------------------------------------------
// Trilinear sampling of the final 64^3 x 32 (8-plane) volume at 65536 coords.
__global__ void __launch_bounds__(256) sample_k(
    const float* __restrict__ coords, const float4* __restrict__ vol4,
    float* __restrict__ out)
{
    int p = blockIdx.x * 256 + threadIdx.x;
    if (p >= 65536) return;
    float fx = (coords[3 * p + 0] + 1.f) * 0.5f * 63.f;
    float fy = (coords[3 * p + 1] + 1.f) * 0.5f * 63.f;
    float fz = (coords[3 * p + 2] + 1.f) * 0.5f * 63.f;
    float x0f = floorf(fx), y0f = floorf(fy), z0f = floorf(fz);
    float tx = fx - x0f, ty = fy - y0f, tz = fz - z0f;
    int x0 = (int)x0f, y0 = (int)y0f, z0 = (int)z0f;
    float acc[32];
    #pragma unroll
    for (int c = 0; c < 32; c++) acc[c] = 0.f;
    #pragma unroll
    for (int dz = 0; dz < 2; dz++)
    #pragma unroll
    for (int dy = 0; dy < 2; dy++)
    #pragma unroll
    for (int dx = 0; dx < 2; dx++) {
        int xi = x0 + dx, yi = y0 + dy, zi = z0 + dz;
        if (xi < 0 || xi >= 64 || yi < 0 || yi >= 64 || zi < 0 || zi >= 64) continue;
        float wgt = (dx ? tx : 1.f - tx) * (dy ? ty : 1.f - ty) * (dz ? tz : 1.f - tz);
        int vi = (zi * 64 + yi) * 64 + xi;
        #pragma unroll
        for (int q = 0; q < 8; q++) {
            float4 v = vol4[(size_t)q * N1 + vi];
            acc[4 * q + 0] += v.x * wgt;
            acc[4 * q + 1] += v.y * wgt;
            acc[4 * q + 2] += v.z * wgt;
            acc[4 * q + 3] += v.w * wgt;
        }
    }
    float4* op = (float4*)(out + (size_t)p * 32);
    #pragma unroll
    for (int q = 0; q < 8; q++)
        op[q] = make_float4(acc[4 * q], acc[4 * q + 1], acc[4 * q + 2], acc[4 * q + 3]);
}

// ---------------------------------------------------------------------------
extern "C" void kernel_launch(void* const* d_in, const int* in_sizes, int n_in,
                              void* d_out, int out_size)
{
    const float* x_feat = (const float*)d_in[0];
    const int*   mask   = (const int*)d_in[1];
    const float* coords = (const float*)d_in[2];
    const float* w0a = (const float*)d_in[3];
    const float* s0a = (const float*)d_in[4];
    const float* b0a = (const float*)d_in[5];
    const float* w0b = (const float*)d_in[6];
    const float* s0b = (const float*)d_in[7];
    const float* b0b = (const float*)d_in[8];
    const float* wd0 = (const float*)d_in[9];
    const float* sd0 = (const float*)d_in[10];
    const float* bd0 = (const float*)d_in[11];
    const float* w1a = (const float*)d_in[12];
    const float* s1a = (const float*)d_in[13];
    const float* b1a = (const float*)d_in[14];
    const float* w1b = (const float*)d_in[15];
    const float* s1b = (const float*)d_in[16];
    const float* b1b = (const float*)d_in[17];
    float* out = (float*)d_out;

    float4 *h0a, *h0b, *h1a, *h1b, *h1c;
    cudaGetSymbolAddress((void**)&h0a, g_h0a);
    cudaGetSymbolAddress((void**)&h0b, g_h0b);
    cudaGetSymbolAddress((void**)&h1a, g_h1a);
    cudaGetSymbolAddress((void**)&h1b, g_h1b);
    cudaGetSymbolAddress((void**)&h1c, g_h1c);

    cudaFuncSetAttribute(conv_down_k<16, 16>,
                         cudaFuncAttributeMaxDynamicSharedMemorySize, 27 * 16 * 16 * 8);
    cudaFuncSetAttribute(conv_same_k<32, 16, 64, 1, false>,
                         cudaFuncAttributeMaxDynamicSharedMemorySize, 27 * 32 * 16 * 8);

    zero_cnt_k<<<1, 1>>>();
    build_list0_k<<<N0 / 256, 256>>>(mask);
    build_list1_k<<<N1 / 256, 256>>>(mask);
    stage1_k<<<N0 / 256, 256>>>(x_feat, mask, w0a, s0a, b0a);
    conv_same_k<16, 8, 128, 0, true>
        <<<N0 / 256, 256, 27 * 16 * 8 * 8>>>(h0a, mask, w0b, s0b, b0b, h0b);
    conv_down_k<16, 16>
        <<<N1 / 256, 256, 27 * 16 * 16 * 8>>>(h0b, mask, wd0, sd0, bd0, h1a);
    conv_same_k<32, 16, 64, 1, false>
        <<<N1 / 256, 256, 27 * 32 * 16 * 8>>>(h1a, nullptr, w1a, s1a, b1a, h1b);
    conv_same_k<32, 16, 64, 1, false>
        <<<N1 / 256, 256, 27 * 32 * 16 * 8>>>(h1b, nullptr, w1b, s1b, b1b, h1c);
    sample_k<<<65536 / 256, 256>>>(coords, h1c, out);
}

// round 5
// speedup vs baseline: 1.5891x; 1.2044x over previous
#include <cuda_runtime.h>

// ---------------------------------------------------------------------------
// SparseConvNet on GB300 — round 3:
//  * level-1 stages are DENSE over 64^3 (94% active anyway), masked in epilogue
//  * 2 x-adjacent voxels per thread: weight-LDS amortized 2x, halo reuse
//  * channel-plane layout [C/4][vox] float4 everywhere (coalesced)
// ---------------------------------------------------------------------------

#define N0 (128*128*128)
#define N1 (64*64*64)

typedef unsigned long long u64;

__device__ float4 g_h0a[4u * N0];   // stage1 out (128^3 x 16) as 4 planes
__device__ float4 g_h0b[4u * N0];   // stage2 out
__device__ float4 g_h1a[8u * N1];   // stage3 out (64^3 x 32) as 8 planes
__device__ float4 g_h1b[8u * N1];   // stage4 out
__device__ float4 g_h1c[8u * N1];   // stage5 out
__device__ int   g_list0[N0];
__device__ int   g_m1[N1];
__device__ int   g_cnt[1];

// ---- packed f32x2 helpers (sm_100+): 2 fp32 FMAs per issue slot -----------
__device__ __forceinline__ u64 pack2(float lo, float hi) {
    u64 d; asm("mov.b64 %0, {%1, %2};" : "=l"(d) : "f"(lo), "f"(hi)); return d;
}
__device__ __forceinline__ void unpack2(u64 v, float& lo, float& hi) {
    asm("mov.b64 {%0, %1}, %2;" : "=f"(lo), "=f"(hi) : "l"(v));
}
__device__ __forceinline__ u64 ffma2(u64 a, u64 b, u64 c) {
    u64 r; asm("fma.rn.f32x2 %0, %1, %2, %3;" : "=l"(r) : "l"(a), "l"(b), "l"(c));
    return r;
}

// ---------------------------------------------------------------------------
__global__ void zero_cnt_k() { g_cnt[0] = 0; }

// Build level-0 active-voxel list (warp-aggregated atomics).
__global__ void build_list0_k(const int* __restrict__ mask) {
    int i = blockIdx.x * blockDim.x + threadIdx.x;
    bool act = mask[i] != 0;
    unsigned b = __ballot_sync(0xffffffffu, act);
    if (!b) return;
    int lane = threadIdx.x & 31;
    int leader = __ffs(b) - 1;
    int pos = 0;
    if (lane == leader) pos = atomicAdd(&g_cnt[0], __popc(b));
    pos = __shfl_sync(0xffffffffu, pos, leader);
    if (act) g_list0[pos + __popc(b & ((1u << lane) - 1u))] = i;
}

// Dense level-1 mask: m1 = maxpool3x3x3 stride2 pad1 of m0.
__global__ void build_m1_k(const int* __restrict__ mask) {
    int i = blockIdx.x * blockDim.x + threadIdx.x;
    int z = i >> 12, y = (i >> 6) & 63, x = i & 63;
    int act = 0;
    #pragma unroll
    for (int t = 0; t < 27; t++) {
        int zz = 2 * z + t / 9 - 1;
        int yy = 2 * y + (t / 3) % 3 - 1;
        int xx = 2 * x + t % 3 - 1;
        if ((unsigned)zz < 128u && (unsigned)yy < 128u && (unsigned)xx < 128u)
            act |= mask[(zz << 14) | (yy << 7) | xx];
    }
    g_m1[i] = act;
}

// ---------------------------------------------------------------------------
// Stage 1: conv 3 -> 16 over masked x_feat (channel-first input), 128^3.
__global__ void __launch_bounds__(256) stage1_k(
    const float* __restrict__ xf, const int* __restrict__ mask,
    const float* __restrict__ w, const float* __restrict__ sc,
    const float* __restrict__ sh)
{
    __shared__ u64 sw[27 * 3 * 8];            // [t][ci][co_pair]
    int n = g_cnt[0];
    if ((int)(blockIdx.x * 256) >= n) return;
    float* swf = (float*)sw;
    for (int idx = threadIdx.x; idx < 16 * 3 * 27; idx += 256) {
        int co = idx / 81, r = idx % 81, ci = r / 27, t = r % 27;
        swf[((t * 3 + ci) * 8 + (co >> 1)) * 2 + (co & 1)] = w[idx];
    }
    __syncthreads();
    int gid = blockIdx.x * 256 + threadIdx.x;
    if (gid >= n) return;
    int vox = g_list0[gid];
    int z = vox >> 14, y = (vox >> 7) & 127, x = vox & 127;
    u64 acc[8];
    #pragma unroll
    for (int p = 0; p < 8; p++) acc[p] = 0ull;
    for (int t = 0; t < 27; t++) {
        int zz = z + t / 9 - 1, yy = y + (t / 3) % 3 - 1, xx = x + t % 3 - 1;
        if ((unsigned)zz >= 128u || (unsigned)yy >= 128u || (unsigned)xx >= 128u) continue;
        int nb = (zz << 14) | (yy << 7) | xx;
        if (!mask[nb]) continue;
        const u64* wp = &sw[t * 24];
        #pragma unroll
        for (int ci = 0; ci < 3; ci++) {
            float xv = xf[(size_t)ci * N0 + nb];
            u64 xv2 = pack2(xv, xv);
            #pragma unroll
            for (int p = 0; p < 8; p++) acc[p] = ffma2(wp[ci * 8 + p], xv2, acc[p]);
        }
    }
    #pragma unroll
    for (int q = 0; q < 4; q++) {
        float a0, a1, a2, a3;
        unpack2(acc[2 * q],     a0, a1);
        unpack2(acc[2 * q + 1], a2, a3);
        float4 o;
        o.x = fmaxf(fmaf(a0, sc[4 * q + 0], sh[4 * q + 0]), 0.f);
        o.y = fmaxf(fmaf(a1, sc[4 * q + 1], sh[4 * q + 1]), 0.f);
        o.z = fmaxf(fmaf(a2, sc[4 * q + 2], sh[4 * q + 2]), 0.f);
        o.w = fmaxf(fmaf(a3, sc[4 * q + 3], sh[4 * q + 3]), 0.f);
        g_h0a[(size_t)q * N0 + vox] = o;
    }
}

// ---------------------------------------------------------------------------
// Stage 2: 16 -> 16 at 128^3, sparse (list0 + per-neighbor mask check).
__global__ void __launch_bounds__(256) stage2_k(
    const float4* __restrict__ in4, const int* __restrict__ mask,
    const float* __restrict__ w, const float* __restrict__ sc,
    const float* __restrict__ sh, float4* __restrict__ out4)
{
    __shared__ u64 sw[27 * 16 * 8];           // [t][ci][co_pair]
    int n = g_cnt[0];
    if ((int)(blockIdx.x * 256) >= n) return;
    float* swf = (float*)sw;
    for (int idx = threadIdx.x; idx < 16 * 16 * 27; idx += 256) {
        int co = idx / (16 * 27), ci = (idx / 27) % 16, t = idx % 27;
        swf[((t * 16 + ci) * 8 + (co >> 1)) * 2 + (co & 1)] = w[idx];
    }
    __syncthreads();
    int gid = blockIdx.x * 256 + threadIdx.x;
    if (gid >= n) return;
    int vox = g_list0[gid];
    int z = vox >> 14, y = (vox >> 7) & 127, x = vox & 127;
    u64 acc[8];
    #pragma unroll
    for (int p = 0; p < 8; p++) acc[p] = 0ull;
    for (int t = 0; t < 27; t++) {
        int zz = z + t / 9 - 1, yy = y + (t / 3) % 3 - 1, xx = x + t % 3 - 1;
        if ((unsigned)zz >= 128u || (unsigned)yy >= 128u || (unsigned)xx >= 128u) continue;
        int nb = (zz << 14) | (yy << 7) | xx;
        if (!mask[nb]) continue;
        float xin[16];
        #pragma unroll
        for (int q = 0; q < 4; q++)
            ((float4*)xin)[q] = in4[(size_t)q * N0 + nb];
        const u64* wp = &sw[t * 16 * 8];
        #pragma unroll
        for (int ci = 0; ci < 16; ci++) {
            u64 xv2 = pack2(xin[ci], xin[ci]);
            #pragma unroll
            for (int p = 0; p < 8; p++) acc[p] = ffma2(wp[ci * 8 + p], xv2, acc[p]);
        }
    }
    #pragma unroll
    for (int q = 0; q < 4; q++) {
        float a0, a1, a2, a3;
        unpack2(acc[2 * q],     a0, a1);
        unpack2(acc[2 * q + 1], a2, a3);
        float4 o;
        o.x = fmaxf(fmaf(a0, sc[4 * q + 0], sh[4 * q + 0]), 0.f);
        o.y = fmaxf(fmaf(a1, sc[4 * q + 1], sh[4 * q + 1]), 0.f);
        o.z = fmaxf(fmaf(a2, sc[4 * q + 2], sh[4 * q + 2]), 0.f);
        o.w = fmaxf(fmaf(a3, sc[4 * q + 3], sh[4 * q + 3]), 0.f);
        out4[(size_t)q * N0 + vox] = o;
    }
}

// ---------------------------------------------------------------------------
// Stage 3: stride-2 conv 16 (128^3, mask-sparse) -> 32 (64^3 dense, m1 mask).
// Each thread computes 2 x-adjacent outputs.
__global__ void __launch_bounds__(256) down2x_k(
    const float4* __restrict__ in4, const int* __restrict__ mask,
    const int* __restrict__ m1, const float* __restrict__ w,
    const float* __restrict__ sc, const float* __restrict__ sh,
    float4* __restrict__ out4)
{
    extern __shared__ u64 sw[];               // [t][ci(16)][co_pair(16)]
    float* swf = (float*)sw;
    for (int idx = threadIdx.x; idx < 32 * 16 * 27; idx += 256) {
        int co = idx / (16 * 27), ci = (idx / 27) % 16, t = idx % 27;
        swf[((t * 16 + ci) * 16 + (co >> 1)) * 2 + (co & 1)] = w[idx];
    }
    __syncthreads();
    int gid = blockIdx.x * 256 + threadIdx.x;
    int vox = gid * 2;
    int z = vox >> 12, y = (vox >> 6) & 63, x = vox & 63;   // x even
    u64 acc0[16], acc1[16];
    #pragma unroll
    for (int p = 0; p < 16; p++) { acc0[p] = 0ull; acc1[p] = 0ull; }
    #pragma unroll
    for (int dzy = 0; dzy < 9; dzy++) {
        int dz = dzy / 3, dy = dzy % 3;
        int zz = 2 * z + dz - 1, yy = 2 * y + dy - 1;
        if ((unsigned)zz >= 128u || (unsigned)yy >= 128u) continue;
        int rb = (zz << 14) | (yy << 7);
        int xbase = 2 * x - 1;
        #pragma unroll
        for (int pos = 0; pos < 5; pos++) {
            int xx = xbase + pos;
            if ((unsigned)xx >= 128u) continue;
            int nb = rb | xx;
            if (!mask[nb]) continue;
            float xin[16];
            #pragma unroll
            for (int q = 0; q < 4; q++)
                ((float4*)xin)[q] = in4[(size_t)q * N0 + nb];
            #pragma unroll
            for (int ci = 0; ci < 16; ci++) {
                u64 xv = pack2(xin[ci], xin[ci]);
                if (pos <= 2) {
                    const u64* wq = &sw[((dzy * 3 + pos) * 16 + ci) * 16];
                    #pragma unroll
                    for (int p = 0; p < 16; p++) acc0[p] = ffma2(wq[p], xv, acc0[p]);
                }
                if (pos >= 2) {
                    const u64* wq = &sw[((dzy * 3 + pos - 2) * 16 + ci) * 16];
                    #pragma unroll
                    for (int p = 0; p < 16; p++) acc1[p] = ffma2(wq[p], xv, acc1[p]);
                }
            }
        }
    }
    float mk0 = (float)m1[vox], mk1 = (float)m1[vox + 1];
    #pragma unroll
    for (int q = 0; q < 8; q++) {
        float a0, a1, a2, a3, b0, b1, b2, b3;
        unpack2(acc0[2 * q],     a0, a1);
        unpack2(acc0[2 * q + 1], a2, a3);
        unpack2(acc1[2 * q],     b0, b1);
        unpack2(acc1[2 * q + 1], b2, b3);
        float4 o0, o1;
        o0.x = fmaxf(fmaf(a0, sc[4 * q + 0], sh[4 * q + 0]), 0.f) * mk0;
        o0.y = fmaxf(fmaf(a1, sc[4 * q + 1], sh[4 * q + 1]), 0.f) * mk0;
        o0.z = fmaxf(fmaf(a2, sc[4 * q + 2], sh[4 * q + 2]), 0.f) * mk0;
        o0.w = fmaxf(fmaf(a3, sc[4 * q + 3], sh[4 * q + 3]), 0.f) * mk0;
        o1.x = fmaxf(fmaf(b0, sc[4 * q + 0], sh[4 * q + 0]), 0.f) * mk1;
        o1.y = fmaxf(fmaf(b1, sc[4 * q + 1], sh[4 * q + 1]), 0.f) * mk1;
        o1.z = fmaxf(fmaf(b2, sc[4 * q + 2], sh[4 * q + 2]), 0.f) * mk1;
        o1.w = fmaxf(fmaf(b3, sc[4 * q + 3], sh[4 * q + 3]), 0.f) * mk1;
        out4[(size_t)q * N1 + vox]     = o0;
        out4[(size_t)q * N1 + vox + 1] = o1;
    }
}

// ---------------------------------------------------------------------------
// Stages 4/5: 32 -> 32 at 64^3, dense, 2 x-adjacent voxels per thread.
__global__ void __launch_bounds__(256) conv64_2x_k(
    const float4* __restrict__ in4, const int* __restrict__ m1,
    const float* __restrict__ w, const float* __restrict__ sc,
    const float* __restrict__ sh, float4* __restrict__ out4)
{
    extern __shared__ u64 sw[];               // [t][ci(32)][co_pair(16)]
    float* swf = (float*)sw;
    for (int idx = threadIdx.x; idx < 32 * 32 * 27; idx += 256) {
        int co = idx / (32 * 27), ci = (idx / 27) % 32, t = idx % 27;
        swf[((t * 32 + ci) * 16 + (co >> 1)) * 2 + (co & 1)] = w[idx];
    }
    __syncthreads();
    int gid = blockIdx.x * 256 + threadIdx.x;
    int vox = gid * 2;
    int z = vox >> 12, y = (vox >> 6) & 63, x = vox & 63;   // x even
    u64 acc0[16], acc1[16];
    #pragma unroll
    for (int p = 0; p < 16; p++) { acc0[p] = 0ull; acc1[p] = 0ull; }
    bool vlo = (x > 0), vhi = (x < 62);
    #pragma unroll 1
    for (int dzy = 0; dzy < 9; dzy++) {
        int dz = dzy / 3, dy = dzy % 3;
        int zz = z + dz - 1, yy = y + dy - 1;
        if ((unsigned)zz >= 64u || (unsigned)yy >= 64u) continue;
        int rb = (zz << 12) | (yy << 6) | x;
        const u64* wt = &sw[(dzy * 3) * 32 * 16];
        #pragma unroll
        for (int q = 0; q < 8; q++) {
            const float4* ip = in4 + (size_t)q * N1 + rb;
            float4 a[4];
            a[0] = vlo ? ip[-1] : make_float4(0.f, 0.f, 0.f, 0.f);
            a[1] = ip[0];
            a[2] = ip[1];
            a[3] = vhi ? ip[2] : make_float4(0.f, 0.f, 0.f, 0.f);
            const float* af = (const float*)a;
            #pragma unroll
            for (int dx = 0; dx < 3; dx++) {
                const u64* wq = wt + (dx * 32 + q * 4) * 16;
                #pragma unroll
                for (int cl = 0; cl < 4; cl++) {
                    u64 x0 = pack2(af[dx * 4 + cl],       af[dx * 4 + cl]);
                    u64 x1 = pack2(af[(dx + 1) * 4 + cl], af[(dx + 1) * 4 + cl]);
                    #pragma unroll
                    for (int p = 0; p < 16; p++) {
                        u64 wv = wq[cl * 16 + p];
                        acc0[p] = ffma2(wv, x0, acc0[p]);
                        acc1[p] = ffma2(wv, x1, acc1[p]);
                    }
                }
            }
        }
    }
    float mk0 = (float)m1[vox], mk1 = (float)m1[vox + 1];
    #pragma unroll
    for (int q = 0; q < 8; q++) {
        float a0, a1, a2, a3, b0, b1, b2, b3;
        unpack2(acc0[2 * q],     a0, a1);
        unpack2(acc0[2 * q + 1], a2, a3);
        unpack2(acc1[2 * q],     b0, b1);
        unpack2(acc1[2 * q + 1], b2, b3);
        float4 o0, o1;
        o0.x = fmaxf(fmaf(a0, sc[4 * q + 0], sh[4 * q + 0]), 0.f) * mk0;
        o0.y = fmaxf(fmaf(a1, sc[4 * q + 1], sh[4 * q + 1]), 0.f) * mk0;
        o0.z = fmaxf(fmaf(a2, sc[4 * q + 2], sh[4 * q + 2]), 0.f) * mk0;
        o0.w = fmaxf(fmaf(a3, sc[4 * q + 3], sh[4 * q + 3]), 0.f) * mk0;
        o1.x = fmaxf(fmaf(b0, sc[4 * q + 0], sh[4 * q + 0]), 0.f) * mk1;
        o1.y = fmaxf(fmaf(b1, sc[4 * q + 1], sh[4 * q + 1]), 0.f) * mk1;
        o1.z = fmaxf(fmaf(b2, sc[4 * q + 2], sh[4 * q + 2]), 0.f) * mk1;
        o1.w = fmaxf(fmaf(b3, sc[4 * q + 3], sh[4 * q + 3]), 0.f) * mk1;
        out4[(size_t)q * N1 + vox]     = o0;
        out4[(size_t)q * N1 + vox + 1] = o1;
    }
}

// ---------------------------------------------------------------------------
// Trilinear sampling of the final 64^3 x 32 (8-plane) volume at 65536 coords.
__global__ void __launch_bounds__(256) sample_k(
    const float* __restrict__ coords, const float4* __restrict__ vol4,
    float* __restrict__ out)
{
    int p = blockIdx.x * 256 + threadIdx.x;
    if (p >= 65536) return;
    float fx = (coords[3 * p + 0] + 1.f) * 0.5f * 63.f;
    float fy = (coords[3 * p + 1] + 1.f) * 0.5f * 63.f;
    float fz = (coords[3 * p + 2] + 1.f) * 0.5f * 63.f;
    float x0f = floorf(fx), y0f = floorf(fy), z0f = floorf(fz);
    float tx = fx - x0f, ty = fy - y0f, tz = fz - z0f;
    int x0 = (int)x0f, y0 = (int)y0f, z0 = (int)z0f;
    float acc[32];
    #pragma unroll
    for (int c = 0; c < 32; c++) acc[c] = 0.f;
    #pragma unroll
    for (int dz = 0; dz < 2; dz++)
    #pragma unroll
    for (int dy = 0; dy < 2; dy++)
    #pragma unroll
    for (int dx = 0; dx < 2; dx++) {
        int xi = x0 + dx, yi = y0 + dy, zi = z0 + dz;
        if (xi < 0 || xi >= 64 || yi < 0 || yi >= 64 || zi < 0 || zi >= 64) continue;
        float wgt = (dx ? tx : 1.f - tx) * (dy ? ty : 1.f - ty) * (dz ? tz : 1.f - tz);
        int vi = (zi * 64 + yi) * 64 + xi;
        #pragma unroll
        for (int q = 0; q < 8; q++) {
            float4 v = vol4[(size_t)q * N1 + vi];
            acc[4 * q + 0] += v.x * wgt;
            acc[4 * q + 1] += v.y * wgt;
            acc[4 * q + 2] += v.z * wgt;
            acc[4 * q + 3] += v.w * wgt;
        }
    }
    float4* op = (float4*)(out + (size_t)p * 32);
    #pragma unroll
    for (int q = 0; q < 8; q++)
        op[q] = make_float4(acc[4 * q], acc[4 * q + 1], acc[4 * q + 2], acc[4 * q + 3]);
}

// ---------------------------------------------------------------------------
extern "C" void kernel_launch(void* const* d_in, const int* in_sizes, int n_in,
                              void* d_out, int out_size)
{
    const float* x_feat = (const float*)d_in[0];
    const int*   mask   = (const int*)d_in[1];
    const float* coords = (const float*)d_in[2];
    const float* w0a = (const float*)d_in[3];
    const float* s0a = (const float*)d_in[4];
    const float* b0a = (const float*)d_in[5];
    const float* w0b = (const float*)d_in[6];
    const float* s0b = (const float*)d_in[7];
    const float* b0b = (const float*)d_in[8];
    const float* wd0 = (const float*)d_in[9];
    const float* sd0 = (const float*)d_in[10];
    const float* bd0 = (const float*)d_in[11];
    const float* w1a = (const float*)d_in[12];
    const float* s1a = (const float*)d_in[13];
    const float* b1a = (const float*)d_in[14];
    const float* w1b = (const float*)d_in[15];
    const float* s1b = (const float*)d_in[16];
    const float* b1b = (const float*)d_in[17];
    float* out = (float*)d_out;

    float4 *h0a, *h0b, *h1a, *h1b, *h1c;
    int *m1p;
    cudaGetSymbolAddress((void**)&h0a, g_h0a);
    cudaGetSymbolAddress((void**)&h0b, g_h0b);
    cudaGetSymbolAddress((void**)&h1a, g_h1a);
    cudaGetSymbolAddress((void**)&h1b, g_h1b);
    cudaGetSymbolAddress((void**)&h1c, g_h1c);
    cudaGetSymbolAddress((void**)&m1p, g_m1);

    cudaFuncSetAttribute(down2x_k,
                         cudaFuncAttributeMaxDynamicSharedMemorySize, 27 * 16 * 16 * 8);
    cudaFuncSetAttribute(conv64_2x_k,
                         cudaFuncAttributeMaxDynamicSharedMemorySize, 27 * 32 * 16 * 8);

    zero_cnt_k<<<1, 1>>>();
    build_list0_k<<<N0 / 256, 256>>>(mask);
    build_m1_k<<<N1 / 256, 256>>>(mask);
    stage1_k<<<N0 / 256, 256>>>(x_feat, mask, w0a, s0a, b0a);
    stage2_k<<<N0 / 256, 256>>>(h0a, mask, w0b, s0b, b0b, h0b);
    down2x_k<<<N1 / 512, 256, 27 * 16 * 16 * 8>>>(h0b, mask, m1p, wd0, sd0, bd0, h1a);
    conv64_2x_k<<<N1 / 512, 256, 27 * 32 * 16 * 8>>>(h1a, m1p, w1a, s1a, b1a, h1b);
    conv64_2x_k<<<N1 / 512, 256, 27 * 32 * 16 * 8>>>(h1b, m1p, w1b, s1b, b1b, h1c);
    sample_k<<<65536 / 256, 256>>>(coords, h1c, out);
}

// round 7
// speedup vs baseline: 1.9035x; 1.1979x over previous
#include <cuda_runtime.h>

// ---------------------------------------------------------------------------
// SparseConvNet on GB300 — round 6 (resubmit of round-5 kernel; R5 bench hit
// node-level cudaErrorSystemNotReady before any kernel ran):
//  * conv64_4x: 4 voxels/thread, co halved per thread -> weight LDS : ffma2 = 1:4
//  * down2x4:   dense (divergence made gating worthless), same 4x structure
//  * channel-plane layout [C/4][vox] float4 everywhere (coalesced)
// ---------------------------------------------------------------------------

#define N0 (128*128*128)
#define N1 (64*64*64)

typedef unsigned long long u64;

__device__ float4 g_h0a[4u * N0];   // stage1 out (128^3 x 16) as 4 planes
__device__ float4 g_h0b[4u * N0];   // stage2 out
__device__ float4 g_h1a[8u * N1];   // stage3 out (64^3 x 32) as 8 planes
__device__ float4 g_h1b[8u * N1];   // stage4 out
__device__ float4 g_h1c[8u * N1];   // stage5 out
__device__ int   g_list0[N0];
__device__ int   g_m1[N1];
__device__ int   g_cnt[1];

// ---- packed f32x2 helpers (sm_100+): 2 fp32 FMAs per issue slot -----------
__device__ __forceinline__ u64 pack2(float lo, float hi) {
    u64 d; asm("mov.b64 %0, {%1, %2};" : "=l"(d) : "f"(lo), "f"(hi)); return d;
}
__device__ __forceinline__ void unpack2(u64 v, float& lo, float& hi) {
    asm("mov.b64 {%0, %1}, %2;" : "=f"(lo), "=f"(hi) : "l"(v));
}
__device__ __forceinline__ u64 ffma2(u64 a, u64 b, u64 c) {
    u64 r; asm("fma.rn.f32x2 %0, %1, %2, %3;" : "=l"(r) : "l"(a), "l"(b), "l"(c));
    return r;
}

// ---------------------------------------------------------------------------
__global__ void zero_cnt_k() { g_cnt[0] = 0; }

__global__ void build_list0_k(const int* __restrict__ mask) {
    int i = blockIdx.x * blockDim.x + threadIdx.x;
    bool act = mask[i] != 0;
    unsigned b = __ballot_sync(0xffffffffu, act);
    if (!b) return;
    int lane = threadIdx.x & 31;
    int leader = __ffs(b) - 1;
    int pos = 0;
    if (lane == leader) pos = atomicAdd(&g_cnt[0], __popc(b));
    pos = __shfl_sync(0xffffffffu, pos, leader);
    if (act) g_list0[pos + __popc(b & ((1u << lane) - 1u))] = i;
}

// Dense level-1 mask: m1 = maxpool3x3x3 stride2 pad1 of m0.
__global__ void build_m1_k(const int* __restrict__ mask) {
    int i = blockIdx.x * blockDim.x + threadIdx.x;
    int z = i >> 12, y = (i >> 6) & 63, x = i & 63;
    int act = 0;
    #pragma unroll
    for (int t = 0; t < 27; t++) {
        int zz = 2 * z + t / 9 - 1;
        int yy = 2 * y + (t / 3) % 3 - 1;
        int xx = 2 * x + t % 3 - 1;
        if ((unsigned)zz < 128u && (unsigned)yy < 128u && (unsigned)xx < 128u)
            act |= mask[(zz << 14) | (yy << 7) | xx];
    }
    g_m1[i] = act;
}

// ---------------------------------------------------------------------------
// Stage 1: conv 3 -> 16 over masked x_feat (channel-first input), 128^3.
__global__ void __launch_bounds__(256) stage1_k(
    const float* __restrict__ xf, const int* __restrict__ mask,
    const float* __restrict__ w, const float* __restrict__ sc,
    const float* __restrict__ sh)
{
    __shared__ u64 sw[27 * 3 * 8];            // [t][ci][co_pair]
    int n = g_cnt[0];
    if ((int)(blockIdx.x * 256) >= n) return;
    float* swf = (float*)sw;
    for (int idx = threadIdx.x; idx < 16 * 3 * 27; idx += 256) {
        int co = idx / 81, r = idx % 81, ci = r / 27, t = r % 27;
        swf[((t * 3 + ci) * 8 + (co >> 1)) * 2 + (co & 1)] = w[idx];
    }
    __syncthreads();
    int gid = blockIdx.x * 256 + threadIdx.x;
    if (gid >= n) return;
    int vox = g_list0[gid];
    int z = vox >> 14, y = (vox >> 7) & 127, x = vox & 127;
    u64 acc[8];
    #pragma unroll
    for (int p = 0; p < 8; p++) acc[p] = 0ull;
    for (int t = 0; t < 27; t++) {
        int zz = z + t / 9 - 1, yy = y + (t / 3) % 3 - 1, xx = x + t % 3 - 1;
        if ((unsigned)zz >= 128u || (unsigned)yy >= 128u || (unsigned)xx >= 128u) continue;
        int nb = (zz << 14) | (yy << 7) | xx;
        if (!mask[nb]) continue;
        const u64* wp = &sw[t * 24];
        #pragma unroll
        for (int ci = 0; ci < 3; ci++) {
            float xv = xf[(size_t)ci * N0 + nb];
            u64 xv2 = pack2(xv, xv);
            #pragma unroll
            for (int p = 0; p < 8; p++) acc[p] = ffma2(wp[ci * 8 + p], xv2, acc[p]);
        }
    }
    #pragma unroll
    for (int q = 0; q < 4; q++) {
        float a0, a1, a2, a3;
        unpack2(acc[2 * q],     a0, a1);
        unpack2(acc[2 * q + 1], a2, a3);
        float4 o;
        o.x = fmaxf(fmaf(a0, sc[4 * q + 0], sh[4 * q + 0]), 0.f);
        o.y = fmaxf(fmaf(a1, sc[4 * q + 1], sh[4 * q + 1]), 0.f);
        o.z = fmaxf(fmaf(a2, sc[4 * q + 2], sh[4 * q + 2]), 0.f);
        o.w = fmaxf(fmaf(a3, sc[4 * q + 3], sh[4 * q + 3]), 0.f);
        g_h0a[(size_t)q * N0 + vox] = o;
    }
}

// ---------------------------------------------------------------------------
// Stage 2: 16 -> 16 at 128^3, sparse (list0 + per-neighbor mask check).
__global__ void __launch_bounds__(256) stage2_k(
    const float4* __restrict__ in4, const int* __restrict__ mask,
    const float* __restrict__ w, const float* __restrict__ sc,
    const float* __restrict__ sh, float4* __restrict__ out4)
{
    __shared__ u64 sw[27 * 16 * 8];           // [t][ci][co_pair]
    int n = g_cnt[0];
    if ((int)(blockIdx.x * 256) >= n) return;
    float* swf = (float*)sw;
    for (int idx = threadIdx.x; idx < 16 * 16 * 27; idx += 256) {
        int co = idx / (16 * 27), ci = (idx / 27) % 16, t = idx % 27;
        swf[((t * 16 + ci) * 8 + (co >> 1)) * 2 + (co & 1)] = w[idx];
    }
    __syncthreads();
    int gid = blockIdx.x * 256 + threadIdx.x;
    if (gid >= n) return;
    int vox = g_list0[gid];
    int z = vox >> 14, y = (vox >> 7) & 127, x = vox & 127;
    u64 acc[8];
    #pragma unroll
    for (int p = 0; p < 8; p++) acc[p] = 0ull;
    for (int t = 0; t < 27; t++) {
        int zz = z + t / 9 - 1, yy = y + (t / 3) % 3 - 1, xx = x + t % 3 - 1;
        if ((unsigned)zz >= 128u || (unsigned)yy >= 128u || (unsigned)xx >= 128u) continue;
        int nb = (zz << 14) | (yy << 7) | xx;
        if (!mask[nb]) continue;
        float xin[16];
        #pragma unroll
        for (int q = 0; q < 4; q++)
            ((float4*)xin)[q] = in4[(size_t)q * N0 + nb];
        const u64* wp = &sw[t * 16 * 8];
        #pragma unroll
        for (int ci = 0; ci < 16; ci++) {
            u64 xv2 = pack2(xin[ci], xin[ci]);
            #pragma unroll
            for (int p = 0; p < 8; p++) acc[p] = ffma2(wp[ci * 8 + p], xv2, acc[p]);
        }
    }
    #pragma unroll
    for (int q = 0; q < 4; q++) {
        float a0, a1, a2, a3;
        unpack2(acc[2 * q],     a0, a1);
        unpack2(acc[2 * q + 1], a2, a3);
        float4 o;
        o.x = fmaxf(fmaf(a0, sc[4 * q + 0], sh[4 * q + 0]), 0.f);
        o.y = fmaxf(fmaf(a1, sc[4 * q + 1], sh[4 * q + 1]), 0.f);
        o.z = fmaxf(fmaf(a2, sc[4 * q + 2], sh[4 * q + 2]), 0.f);
        o.w = fmaxf(fmaf(a3, sc[4 * q + 3], sh[4 * q + 3]), 0.f);
        out4[(size_t)q * N0 + vox] = o;
    }
}

// ---------------------------------------------------------------------------
// Stage 3: DENSE stride-2 conv 16 (128^3) -> 32 (64^3), m1 mask in epilogue.
// Input h0b is exactly zero at inactive voxels, so no gating needed.
// Thread = 4 x-adjacent outputs x one co-half (16 of 32 channels).
__global__ void __launch_bounds__(256) down2x4_k(
    const float4* __restrict__ in4, const int* __restrict__ m1,
    const float* __restrict__ w, const float* __restrict__ sc,
    const float* __restrict__ sh, float4* __restrict__ out4)
{
    extern __shared__ u64 sw[];               // [t(27)][ci(16)][copair(16)]
    float* swf = (float*)sw;
    for (int idx = threadIdx.x; idx < 32 * 16 * 27; idx += 256) {
        int co = idx / (16 * 27), ci = (idx / 27) % 16, t = idx % 27;
        swf[((t * 16 + ci) * 16 + (co >> 1)) * 2 + (co & 1)] = w[idx];
    }
    __syncthreads();
    int gid  = blockIdx.x * 256 + threadIdx.x;
    int half = gid & 1;
    int vox  = (gid >> 1) * 4;
    int z = vox >> 12, y = (vox >> 6) & 63, x = vox & 63;   // x multiple of 4
    u64 acc[4][8];
    #pragma unroll
    for (int v = 0; v < 4; v++)
        #pragma unroll
        for (int p = 0; p < 8; p++) acc[v][p] = 0ull;
    bool vlo = (x > 0), vhi = (x < 60);
    const float4 z4 = make_float4(0.f, 0.f, 0.f, 0.f);
    #pragma unroll 1
    for (int dzy = 0; dzy < 9; dzy++) {
        int dz = dzy / 3, dy = dzy % 3;
        int zz = 2 * z + dz - 1, yy = 2 * y + dy - 1;
        if ((unsigned)zz >= 128u || (unsigned)yy >= 128u) continue;
        int rb = (zz << 14) | (yy << 7) | (2 * x);
        const u64* wt = &sw[(dzy * 3) * 16 * 16 + half * 8];
        #pragma unroll 1
        for (int q = 0; q < 4; q++) {
            const float4* ip = in4 + (size_t)q * N0 + rb;
            float4 a[10];                      // input x-positions 2x-1 .. 2x+8
            a[0] = vlo ? ip[-1] : z4;
            #pragma unroll
            for (int j = 1; j < 9; j++) a[j] = ip[j - 1];
            a[9] = vhi ? ip[8] : z4;
            const float* af = (const float*)a;
            #pragma unroll
            for (int dx = 0; dx < 3; dx++) {
                const u64* wq = wt + (dx * 16 + q * 4) * 16;
                #pragma unroll
                for (int cl = 0; cl < 4; cl++) {
                    // output voxel v uses input position 2v+dx (rel. 2x-1)
                    u64 x0 = pack2(af[(0 + dx) * 4 + cl], af[(0 + dx) * 4 + cl]);
                    u64 x1 = pack2(af[(2 + dx) * 4 + cl], af[(2 + dx) * 4 + cl]);
                    u64 x2 = pack2(af[(4 + dx) * 4 + cl], af[(4 + dx) * 4 + cl]);
                    u64 x3 = pack2(af[(6 + dx) * 4 + cl], af[(6 + dx) * 4 + cl]);
                    #pragma unroll
                    for (int p = 0; p < 8; p++) {
                        u64 wv = wq[cl * 16 + p];
                        acc[0][p] = ffma2(wv, x0, acc[0][p]);
                        acc[1][p] = ffma2(wv, x1, acc[1][p]);
                        acc[2][p] = ffma2(wv, x2, acc[2][p]);
                        acc[3][p] = ffma2(wv, x3, acc[3][p]);
                    }
                }
            }
        }
    }
    const float* scb = sc + 16 * half;
    const float* shb = sh + 16 * half;
    #pragma unroll
    for (int v = 0; v < 4; v++) {
        float mk = (float)m1[vox + v];
        #pragma unroll
        for (int qq = 0; qq < 4; qq++) {
            float a0, a1, a2, a3;
            unpack2(acc[v][2 * qq],     a0, a1);
            unpack2(acc[v][2 * qq + 1], a2, a3);
            float4 o;
            o.x = fmaxf(fmaf(a0, scb[4 * qq + 0], shb[4 * qq + 0]), 0.f) * mk;
            o.y = fmaxf(fmaf(a1, scb[4 * qq + 1], shb[4 * qq + 1]), 0.f) * mk;
            o.z = fmaxf(fmaf(a2, scb[4 * qq + 2], shb[4 * qq + 2]), 0.f) * mk;
            o.w = fmaxf(fmaf(a3, scb[4 * qq + 3], shb[4 * qq + 3]), 0.f) * mk;
            out4[(size_t)(4 * half + qq) * N1 + vox + v] = o;
        }
    }
}

// ---------------------------------------------------------------------------
// Stages 4/5: 32 -> 32 at 64^3 dense.
// Thread = 4 x-adjacent voxels x one co-half (16 of 32 channels).
__global__ void __launch_bounds__(256) conv64_4x_k(
    const float4* __restrict__ in4, const int* __restrict__ m1,
    const float* __restrict__ w, const float* __restrict__ sc,
    const float* __restrict__ sh, float4* __restrict__ out4)
{
    extern __shared__ u64 sw[];               // [t(27)][ci(32)][copair(16)]
    float* swf = (float*)sw;
    for (int idx = threadIdx.x; idx < 32 * 32 * 27; idx += 256) {
        int co = idx / (32 * 27), ci = (idx / 27) % 32, t = idx % 27;
        swf[((t * 32 + ci) * 16 + (co >> 1)) * 2 + (co & 1)] = w[idx];
    }
    __syncthreads();
    int gid  = blockIdx.x * 256 + threadIdx.x;
    int half = gid & 1;
    int vox  = (gid >> 1) * 4;
    int z = vox >> 12, y = (vox >> 6) & 63, x = vox & 63;   // x multiple of 4
    u64 acc[4][8];
    #pragma unroll
    for (int v = 0; v < 4; v++)
        #pragma unroll
        for (int p = 0; p < 8; p++) acc[v][p] = 0ull;
    bool vlo = (x > 0), vhi = (x < 60);
    const float4 z4 = make_float4(0.f, 0.f, 0.f, 0.f);
    #pragma unroll 1
    for (int dzy = 0; dzy < 9; dzy++) {
        int dz = dzy / 3, dy = dzy % 3;
        int zz = z + dz - 1, yy = y + dy - 1;
        if ((unsigned)zz >= 64u || (unsigned)yy >= 64u) continue;
        int rb = (zz << 12) | (yy << 6) | x;
        const u64* wt = &sw[(dzy * 3) * 32 * 16 + half * 8];
        #pragma unroll 1
        for (int q = 0; q < 8; q++) {
            const float4* ip = in4 + (size_t)q * N1 + rb;
            float4 a[6];                       // x-positions x-1 .. x+4
            a[0] = vlo ? ip[-1] : z4;
            a[1] = ip[0]; a[2] = ip[1]; a[3] = ip[2]; a[4] = ip[3];
            a[5] = vhi ? ip[4] : z4;
            const float* af = (const float*)a;
            #pragma unroll
            for (int dx = 0; dx < 3; dx++) {
                const u64* wq = wt + (dx * 32 + q * 4) * 16;
                #pragma unroll
                for (int cl = 0; cl < 4; cl++) {
                    u64 x0 = pack2(af[(0 + dx) * 4 + cl], af[(0 + dx) * 4 + cl]);
                    u64 x1 = pack2(af[(1 + dx) * 4 + cl], af[(1 + dx) * 4 + cl]);
                    u64 x2 = pack2(af[(2 + dx) * 4 + cl], af[(2 + dx) * 4 + cl]);
                    u64 x3 = pack2(af[(3 + dx) * 4 + cl], af[(3 + dx) * 4 + cl]);
                    #pragma unroll
                    for (int p = 0; p < 8; p++) {
                        u64 wv = wq[cl * 16 + p];
                        acc[0][p] = ffma2(wv, x0, acc[0][p]);
                        acc[1][p] = ffma2(wv, x1, acc[1][p]);
                        acc[2][p] = ffma2(wv, x2, acc[2][p]);
                        acc[3][p] = ffma2(wv, x3, acc[3][p]);
                    }
                }
            }
        }
    }
    const float* scb = sc + 16 * half;
    const float* shb = sh + 16 * half;
    #pragma unroll
    for (int v = 0; v < 4; v++) {
        float mk = (float)m1[vox + v];
        #pragma unroll
        for (int qq = 0; qq < 4; qq++) {
            float a0, a1, a2, a3;
            unpack2(acc[v][2 * qq],     a0, a1);
            unpack2(acc[v][2 * qq + 1], a2, a3);
            float4 o;
            o.x = fmaxf(fmaf(a0, scb[4 * qq + 0], shb[4 * qq + 0]), 0.f) * mk;
            o.y = fmaxf(fmaf(a1, scb[4 * qq + 1], shb[4 * qq + 1]), 0.f) * mk;
            o.z = fmaxf(fmaf(a2, scb[4 * qq + 2], shb[4 * qq + 2]), 0.f) * mk;
            o.w = fmaxf(fmaf(a3, scb[4 * qq + 3], shb[4 * qq + 3]), 0.f) * mk;
            out4[(size_t)(4 * half + qq) * N1 + vox + v] = o;
        }
    }
}

// ---------------------------------------------------------------------------
// Trilinear sampling of the final 64^3 x 32 (8-plane) volume at 65536 coords.
__global__ void __launch_bounds__(256) sample_k(
    const float* __restrict__ coords, const float4* __restrict__ vol4,
    float* __restrict__ out)
{
    int p = blockIdx.x * 256 + threadIdx.x;
    if (p >= 65536) return;
    float fx = (coords[3 * p + 0] + 1.f) * 0.5f * 63.f;
    float fy = (coords[3 * p + 1] + 1.f) * 0.5f * 63.f;
    float fz = (coords[3 * p + 2] + 1.f) * 0.5f * 63.f;
    float x0f = floorf(fx), y0f = floorf(fy), z0f = floorf(fz);
    float tx = fx - x0f, ty = fy - y0f, tz = fz - z0f;
    int x0 = (int)x0f, y0 = (int)y0f, z0 = (int)z0f;
    float acc[32];
    #pragma unroll
    for (int c = 0; c < 32; c++) acc[c] = 0.f;
    #pragma unroll
    for (int dz = 0; dz < 2; dz++)
    #pragma unroll
    for (int dy = 0; dy < 2; dy++)
    #pragma unroll
    for (int dx = 0; dx < 2; dx++) {
        int xi = x0 + dx, yi = y0 + dy, zi = z0 + dz;
        if (xi < 0 || xi >= 64 || yi < 0 || yi >= 64 || zi < 0 || zi >= 64) continue;
        float wgt = (dx ? tx : 1.f - tx) * (dy ? ty : 1.f - ty) * (dz ? tz : 1.f - tz);
        int vi = (zi * 64 + yi) * 64 + xi;
        #pragma unroll
        for (int q = 0; q < 8; q++) {
            float4 v = vol4[(size_t)q * N1 + vi];
            acc[4 * q + 0] += v.x * wgt;
            acc[4 * q + 1] += v.y * wgt;
            acc[4 * q + 2] += v.z * wgt;
            acc[4 * q + 3] += v.w * wgt;
        }
    }
    float4* op = (float4*)(out + (size_t)p * 32);
    #pragma unroll
    for (int q = 0; q < 8; q++)
        op[q] = make_float4(acc[4 * q], acc[4 * q + 1], acc[4 * q + 2], acc[4 * q + 3]);
}

// ---------------------------------------------------------------------------
extern "C" void kernel_launch(void* const* d_in, const int* in_sizes, int n_in,
                              void* d_out, int out_size)
{
    const float* x_feat = (const float*)d_in[0];
    const int*   mask   = (const int*)d_in[1];
    const float* coords = (const float*)d_in[2];
    const float* w0a = (const float*)d_in[3];
    const float* s0a = (const float*)d_in[4];
    const float* b0a = (const float*)d_in[5];
    const float* w0b = (const float*)d_in[6];
    const float* s0b = (const float*)d_in[7];
    const float* b0b = (const float*)d_in[8];
    const float* wd0 = (const float*)d_in[9];
    const float* sd0 = (const float*)d_in[10];
    const float* bd0 = (const float*)d_in[11];
    const float* w1a = (const float*)d_in[12];
    const float* s1a = (const float*)d_in[13];
    const float* b1a = (const float*)d_in[14];
    const float* w1b = (const float*)d_in[15];
    const float* s1b = (const float*)d_in[16];
    const float* b1b = (const float*)d_in[17];
    float* out = (float*)d_out;

    float4 *h0a, *h0b, *h1a, *h1b, *h1c;
    int *m1p;
    cudaGetSymbolAddress((void**)&h0a, g_h0a);
    cudaGetSymbolAddress((void**)&h0b, g_h0b);
    cudaGetSymbolAddress((void**)&h1a, g_h1a);
    cudaGetSymbolAddress((void**)&h1b, g_h1b);
    cudaGetSymbolAddress((void**)&h1c, g_h1c);
    cudaGetSymbolAddress((void**)&m1p, g_m1);

    cudaFuncSetAttribute(down2x4_k,
                         cudaFuncAttributeMaxDynamicSharedMemorySize, 27 * 16 * 16 * 8);
    cudaFuncSetAttribute(conv64_4x_k,
                         cudaFuncAttributeMaxDynamicSharedMemorySize, 27 * 32 * 16 * 8);

    zero_cnt_k<<<1, 1>>>();
    build_list0_k<<<N0 / 256, 256>>>(mask);
    build_m1_k<<<N1 / 256, 256>>>(mask);
    stage1_k<<<N0 / 256, 256>>>(x_feat, mask, w0a, s0a, b0a);
    stage2_k<<<N0 / 256, 256>>>(h0a, mask, w0b, s0b, b0b, h0b);
    // threads = (N1/4 voxel-groups) * 2 co-halves = 131072
    down2x4_k<<<512, 256, 27 * 16 * 16 * 8>>>(h0b, m1p, wd0, sd0, bd0, h1a);
    conv64_4x_k<<<512, 256, 27 * 32 * 16 * 8>>>(h1a, m1p, w1a, s1a, b1a, h1b);
    conv64_4x_k<<<512, 256, 27 * 32 * 16 * 8>>>(h1b, m1p, w1b, s1b, b1b, h1c);
    sample_k<<<65536 / 256, 256>>>(coords, h1c, out);
}